// round 5
// baseline (speedup 1.0000x reference)
#include <cuda_runtime.h>
#include <math.h>

#define NN 1000
#define FF 128
#define TT 4
#define PP 10
#define DD 13
#define EE 20000
#define EAD 16
#define HH 128
#define KK 64
#define NDIM 13000        // N*D
#define IEDGE 169
#define INODE 91
#define WNS 172           // padded Wn row stride (mult of 4)
#define WCPAD 68          // padded Wc smem row stride (17 float4 groups, odd -> no bank conflicts)
#define WPPAD 132         // padded Wp smem row stride (33 float4 groups, odd)
#define TOT4 42250000     // 169e6 floats / 4
#define NODES8 8

// ---------------- scratch (device globals; no runtime allocation) ----------------
__device__ __align__(16) float g_m[NN*FF];
__device__ float g_base[NN*FF];
__device__ float g_r1[NN*HH];
__device__ float g_r2[NN*HH];
__device__ float g_q1[NN*KK];
__device__ float g_q2[NN*KK];
__device__ __align__(16) float g_Wn[TT*FF*WNS];     // [t][f][xy(pad 172)] = W_node @ cob_node
__device__ __align__(16) float g_WcT[PP*IEDGE*KK];  // [p][xy][k]          = (W_edge @ cob_edge)^T
__device__ __align__(16) float g_h[EE*2*KK];        // per-edge [h_ij(64) | h_ji(64)]
__device__ float g_nblk[NN*IEDGE];                  // node diagonal blocks
__device__ int   g_off[PP+1];
__device__ int   g_bucket[EE];
__device__ int   g_rowoff[NN+1];
__device__ int   g_rentry[2*EE];                    // e*2 | flag (flag=1 -> neighbor is src)

// ---------------- zero the whole output (parallel graph branch) ----------------
__global__ void k_zero(float4* __restrict__ M4) {
    int idx = blockIdx.x*blockDim.x + threadIdx.x;
    int nth = gridDim.x*blockDim.x;
    float4 z = make_float4(0.f, 0.f, 0.f, 0.f);
    for (int i = idx; i < TOT4; i += nth) M4[i] = z;
}

// ---------------- fused change-of-basis weights, coalesced tiled form ----------------
// grid 32: (t in 4) x (f-chunk of 16 in 8). out[f][xy] = sum_i W[f][i] * cob[i][xy]
__global__ void __launch_bounds__(192) k_pre_node(const float* __restrict__ Wnode,
                                                  const float* __restrict__ cobn) {
    int t  = blockIdx.x & 3;
    int f0 = (blockIdx.x >> 2) * 16;
    int tid = threadIdx.x;   // 192
    __shared__ float Ws[INODE][17];   // [i][f] padded
    for (int j = tid; j < 16*INODE; j += 192) {
        int f = j / INODE, i = j % INODE;
        Ws[i][f] = Wnode[(t*FF + f0 + f)*INODE + i];
    }
    for (int j = tid; j < 16*3; j += 192)      // zero pad cols so float4 reads are benign
        g_Wn[(t*FF + f0 + j/3)*WNS + IEDGE + (j % 3)] = 0.f;
    __syncthreads();
    if (tid >= IEDGE) return;
    float acc[16];
    #pragma unroll
    for (int f = 0; f < 16; f++) acc[f] = 0.f;
    for (int i = 0; i < INODE; i++) {
        float cv = cobn[(t*INODE + i)*IEDGE + tid];   // coalesced
        #pragma unroll
        for (int f = 0; f < 16; f++) acc[f] += cv * Ws[i][f];
    }
    #pragma unroll
    for (int f = 0; f < 16; f++) g_Wn[(t*FF + f0 + f)*WNS + tid] = acc[f];
}

// grid 40: (p in 10) x (k-chunk of 16 in 4). WcT[xy][k] = sum_i W[k][i] * cob[i][xy]
__global__ void __launch_bounds__(192) k_pre_edge(const float* __restrict__ Wedge,
                                                  const float* __restrict__ cobe) {
    int p  = blockIdx.x >> 2;
    int k0 = (blockIdx.x & 3) * 16;
    int tid = threadIdx.x;   // 192
    __shared__ float Ws[IEDGE][17];   // [i][k] padded
    for (int j = tid; j < 16*IEDGE; j += 192) {
        int k = j / IEDGE, i = j % IEDGE;
        Ws[i][k] = Wedge[(p*KK + k0 + k)*IEDGE + i];
    }
    __syncthreads();
    if (tid >= IEDGE) return;
    float acc[16];
    #pragma unroll
    for (int k = 0; k < 16; k++) acc[k] = 0.f;
    for (int i = 0; i < IEDGE; i++) {
        float cv = cobe[((size_t)p*IEDGE + i)*IEDGE + tid];   // coalesced
        #pragma unroll
        for (int k = 0; k < 16; k++) acc[k] += cv * Ws[i][k];
    }
    float4* dst = (float4*)&g_WcT[(p*IEDGE + tid)*KK + k0];
    #pragma unroll
    for (int k4 = 0; k4 < 4; k4++)
        dst[k4] = make_float4(acc[4*k4], acc[4*k4+1], acc[4*k4+2], acc[4*k4+3]);
}

// ---------------- node prep: m = nf@Wmsg, base = nf + na@Wattr ----------------
__global__ void k_node_prep(const float* __restrict__ nf, const float* __restrict__ na,
                            const float* __restrict__ Wmsg, const float* __restrict__ Wattr) {
    int n = blockIdx.x;
    int f = threadIdx.x;   // 128
    int gt = n*FF + f;
    __shared__ float row[FF];
    row[f] = nf[gt];
    __syncthreads();
    float acc = 0.f;
    #pragma unroll 8
    for (int g = 0; g < FF; g++) acc += row[g] * Wmsg[g*FF + f];
    g_m[gt] = acc;
    float b = row[f];
    #pragma unroll
    for (int t = 0; t < TT; t++) b += na[n*TT + t] * Wattr[t*FF + f];
    g_base[gt] = b;
}

// ---------------- fused hist + scan + bucket (single CTA, smem counters) ----------------
__global__ void __launch_bounds__(1024) k_index(const int* __restrict__ ei,
                                                const int* __restrict__ et) {
    __shared__ int rc[1024];
    __shared__ int tc[PP], tcur[PP];
    int tid = threadIdx.x;
    rc[tid] = 0;
    if (tid < PP) tc[tid] = 0;
    __syncthreads();
    for (int e = tid; e < EE; e += 1024) {
        atomicAdd(&rc[ei[e]], 1);
        atomicAdd(&rc[ei[EE + e]], 1);
        atomicAdd(&tc[et[e]], 1);
    }
    __syncthreads();
    int v = rc[tid];
    #pragma unroll
    for (int off = 1; off < 1024; off <<= 1) {
        int t = (tid >= off) ? rc[tid - off] : 0;
        __syncthreads();
        rc[tid] += t;
        __syncthreads();
    }
    int excl = rc[tid] - v;
    if (tid < NN) g_rowoff[tid] = excl;
    if (tid == NN - 1) g_rowoff[NN] = rc[tid];
    __syncthreads();
    rc[tid] = excl;                          // reuse as row cursors
    if (tid == 0) {
        int a = 0;
        for (int p = 0; p < PP; p++) { g_off[p] = a; tcur[p] = a; a += tc[p]; }
        g_off[PP] = a;
    }
    __syncthreads();
    for (int e = tid; e < EE; e += 1024) {
        int p = et[e];
        g_bucket[atomicAdd(&tcur[p], 1)] = e;
        int s = ei[e], d = ei[EE + e];
        g_rentry[atomicAdd(&rc[s], 1)] = e*2;       // row s, neighbor = dst
        g_rentry[atomicAdd(&rc[d], 1)] = e*2 + 1;   // row d, neighbor = src
    }
}

// ---------------- per-node outputs, 8 nodes per CTA, gather fused ----------------
__global__ void __launch_bounds__(160) k_node_out(const float* __restrict__ Wem,
                                                  const float* __restrict__ Wproj,
                                                  const int* __restrict__ ntype,
                                                  const int* __restrict__ ei) {
    int nb  = blockIdx.x * NODES8;     // 125 blocks
    int tid = threadIdx.x;             // 160
    __shared__ float nh[NODES8][FF];
    __shared__ int types[NODES8];
    if (tid < FF) {
        for (int m = 0; m < NODES8; m++) {
            int n = nb + m;
            float acc = 0.f;
            int lo = g_rowoff[n], hi = g_rowoff[n+1];
            for (int q = lo; q < hi; q++) {
                int v = g_rentry[q];                 // broadcast
                int e = v >> 1;
                int other = (v & 1) ? ei[e] : ei[EE + e];
                acc += g_m[other*FF + tid];
            }
            nh[m][tid] = g_base[n*FF + tid] + acc * 0.05f;
        }
    }
    if (tid < NODES8) types[tid] = ntype[nb + tid];
    __syncthreads();
    int o = tid;
    if (o >= 139) return;              // 32 r1 + 32 r2 + 16 q1 + 16 q2 + 43 nblk tasks
    const float4* w4 = 0; int stride4 = 0, kind, c0;
    if (o < 32)      { c0 = o*4;        w4 = (const float4*)(Wem + c0);             stride4 = HH/4; kind = 0; }
    else if (o < 64) { c0 = (o-32)*4;   w4 = (const float4*)(Wem + FF*HH + c0);     stride4 = HH/4; kind = 1; }
    else if (o < 80) { c0 = (o-64)*4;   w4 = (const float4*)(Wproj + FF*KK + c0);   stride4 = KK/4; kind = 2; }
    else if (o < 96) { c0 = (o-80)*4;   w4 = (const float4*)(Wproj + 2*FF*KK + c0); stride4 = KK/4; kind = 3; }
    else             { c0 = (o-96)*4;   kind = 4; }
    float4 acc[NODES8];
    #pragma unroll
    for (int m = 0; m < NODES8; m++) acc[m] = make_float4(0.f,0.f,0.f,0.f);
    if (kind < 4) {
        #pragma unroll 4
        for (int g = 0; g < FF; g++) {
            float4 w = w4[g*stride4];
            #pragma unroll
            for (int m = 0; m < NODES8; m++) {
                float h = nh[m][g];
                acc[m].x += h*w.x; acc[m].y += h*w.y; acc[m].z += h*w.z; acc[m].w += h*w.w;
            }
        }
    } else {
        const float4* wn[NODES8];
        #pragma unroll
        for (int m = 0; m < NODES8; m++) wn[m] = (const float4*)(g_Wn + types[m]*FF*WNS + c0);
        for (int g = 0; g < FF; g++) {
            #pragma unroll
            for (int m = 0; m < NODES8; m++) {
                float4 w = wn[m][g*(WNS/4)];
                float h = nh[m][g];
                acc[m].x += h*w.x; acc[m].y += h*w.y; acc[m].z += h*w.z; acc[m].w += h*w.w;
            }
        }
    }
    #pragma unroll
    for (int m = 0; m < NODES8; m++) {
        int n = nb + m;
        if (kind == 0)      *(float4*)&g_r1[n*HH + c0] = acc[m];
        else if (kind == 1) *(float4*)&g_r2[n*HH + c0] = acc[m];
        else if (kind == 2) *(float4*)&g_q1[n*KK + c0] = acc[m];
        else if (kind == 3) *(float4*)&g_q2[n*KK + c0] = acc[m];
        else {
            float v[4] = {acc[m].x, acc[m].y, acc[m].z, acc[m].w};
            #pragma unroll
            for (int j = 0; j < 4; j++) {
                int xy = c0 + j;
                if (xy < IEDGE) g_nblk[n*IEDGE + xy] = v[j];
            }
        }
    }
}

// ---------------- per-edge: edge_msg -> u -> h_ij/h_ji (4 edges per iteration) ----------------
__global__ void __launch_bounds__(128) k_edge_msg(const float* __restrict__ ef, const float* __restrict__ ea,
                                                  const float* __restrict__ Wem, const float* __restrict__ Wproj,
                                                  const int* __restrict__ ei) {
    __shared__ __align__(16) float wp[KK*WPPAD];   // [c(64)][g(128) pad 132] W_proj rows 0..127 transposed
    __shared__ __align__(16) float msg[4][HH];
    __shared__ float eatt[4][32];
    __shared__ int sd[8];
    int tid = threadIdx.x;   // 128
    float emreg[32];         // column tid of W_em rows 256..287 (edge feats/attrs part)
    #pragma unroll
    for (int j = 0; j < 32; j++) emreg[j] = Wem[(2*FF + j)*HH + tid];
    for (int i = tid; i < FF*KK; i += 128) {
        int r = i >> 6, c = i & 63;       // coalesced read of Wproj, transpose into smem
        wp[c*WPPAD + r] = Wproj[i];
    }
    __syncthreads();
    for (int grp = blockIdx.x; grp < EE/4; grp += gridDim.x) {
        int e0 = grp*4;
        {
            int el = tid >> 5, j = tid & 31;
            eatt[el][j] = (j < EAD) ? ef[(e0+el)*EAD + j] : ea[(e0+el)*EAD + (j - EAD)];
        }
        if (tid < 8) sd[tid] = ei[(tid & 1)*EE + e0 + (tid >> 1)];
        __syncthreads();
        #pragma unroll
        for (int el = 0; el < 4; el++) {
            float fe = 0.f;
            #pragma unroll
            for (int j = 0; j < 32; j++) fe += eatt[el][j]*emreg[j];
            float pre = g_r1[sd[2*el]*HH + tid] + g_r2[sd[2*el+1]*HH + tid] + fe;
            float ex = __expf(2.f*pre);                  // tanh = 1 - 2/(e^{2x}+1)
            msg[el][tid] = 1.f - __fdividef(2.f, ex + 1.f);
        }
        __syncthreads();
        int c = tid & 63, hh = tid >> 6;
        const float4* wr = (const float4*)&wp[c*WPPAD];
        const float4* m0 = (const float4*)msg[2*hh];
        const float4* m1 = (const float4*)msg[2*hh + 1];
        float u0 = 0.f, u1 = 0.f;
        #pragma unroll 8
        for (int g = 0; g < HH/4; g++) {
            float4 w = wr[g]; float4 a = m0[g]; float4 b = m1[g];
            u0 += w.x*a.x + w.y*a.y + w.z*a.z + w.w*a.w;
            u1 += w.x*b.x + w.y*b.y + w.z*b.z + w.w*b.w;
        }
        #pragma unroll
        for (int q = 0; q < 2; q++) {
            int el = 2*hh + q;
            float u = q ? u1 : u0;
            int e = e0 + el, s = sd[2*el], d = sd[2*el + 1];
            g_h[e*2*KK + c]      = u + g_q1[s*KK + c] + g_q2[d*KK + c];
            g_h[e*2*KK + KK + c] = u + g_q1[d*KK + c] + g_q2[s*KK + c];
        }
        __syncthreads();
    }
}

// ---------------- per-edge 13x13 blocks -> atomic scatter into zeroed M (+ diag blocks) ----------------
__global__ void k_edge_blocks(const int* __restrict__ ei, float* __restrict__ M) {
    int p   = blockIdx.y;
    int tid = threadIdx.x;   // 192
    if (p == PP) {           // diagonal node blocks
        int n0 = blockIdx.x * 16;
        int n1 = min(n0 + 16, NN);
        for (int n = n0; n < n1; n++)
            for (int j = tid; j < IEDGE; j += 192) {
                int x = j/DD, y = j - x*DD;
                atomicAdd(&M[(size_t)(n*DD + x)*NDIM + n*DD + y], g_nblk[n*IEDGE + j]);
            }
        return;
    }
    __shared__ __align__(16) float wc[IEDGE*WCPAD];   // [xy][k pad 68]
    __shared__ __align__(16) float hsm[4*2*KK];       // 4 edges x [h_ij|h_ji]
    __shared__ int einfo[8];
    int beg = g_off[p], end = g_off[p+1];
    int cnt = end - beg;
    int per = (cnt + gridDim.x - 1) / gridDim.x;
    int lo  = beg + blockIdx.x * per;
    int hi  = min(lo + per, end);
    if (lo >= hi) return;   // uniform per block
    const float* srcw = g_WcT + p*IEDGE*KK;
    for (int i = tid; i < IEDGE*(KK/4); i += blockDim.x) {
        int xy = i >> 4, kk = i & 15;
        ((float4*)(wc + xy*WCPAD))[kk] = ((const float4*)(srcw + xy*KK))[kk];
    }
    __syncthreads();
    int x = 0, y = 0, xyt = 0;
    if (tid < IEDGE) { x = tid/DD; y = tid - x*DD; xyt = y*DD + x; }
    for (int base = lo; base < hi; base += 4) {
        int ne = min(4, hi - base);
        for (int i = tid; i < 4*2*KK; i += blockDim.x) {
            int el = i >> 7, off = i & 127;
            float v = 0.f;
            if (el < ne) v = g_h[(size_t)g_bucket[base + el]*2*KK + off];
            hsm[i] = v;
        }
        if (tid < 8) {
            int el = tid >> 1;
            int e = g_bucket[base + min(el, ne - 1)];
            einfo[tid] = ei[(tid & 1)*EE + e];
        }
        __syncthreads();
        if (tid < IEDGE) {
            const float4* wf = (const float4*)(wc + tid*WCPAD);
            const float4* wt = (const float4*)(wc + xyt*WCPAD);
            const float4* h4 = (const float4*)hsm;
            float a[4] = {0.f,0.f,0.f,0.f}, b[4] = {0.f,0.f,0.f,0.f};
            #pragma unroll
            for (int kk = 0; kk < KK/4; kk++) {
                float4 f = wf[kk], t = wt[kk];
                #pragma unroll
                for (int el = 0; el < 4; el++) {
                    float4 hf = h4[el*32 + kk];        // h_ij
                    float4 hb = h4[el*32 + 16 + kk];   // h_ji
                    a[el] += hf.x*f.x + hf.y*f.y + hf.z*f.z + hf.w*f.w;
                    b[el] += hb.x*t.x + hb.y*t.y + hb.z*t.z + hb.w*t.w;
                }
            }
            #pragma unroll
            for (int el = 0; el < 4; el++) {
                if (el < ne) {
                    float v = 0.5f*(a[el] + b[el]);
                    int s = einfo[2*el], d = einfo[2*el + 1];
                    atomicAdd(&M[(size_t)(s*DD + x)*NDIM + d*DD + y], v);
                    atomicAdd(&M[(size_t)(d*DD + y)*NDIM + s*DD + x], v);
                }
            }
        }
        __syncthreads();
    }
}

// ---------------- launcher: fork-join graph; streams/events created once (call 1 = correctness run) ----------------
extern "C" void kernel_launch(void* const* d_in, const int* in_sizes, int n_in,
                              void* d_out, int out_size) {
    const float* nf    = (const float*)d_in[0];
    const float* na    = (const float*)d_in[1];
    const float* ef    = (const float*)d_in[2];
    const float* ea    = (const float*)d_in[3];
    const int*   ei    = (const int*)d_in[4];
    const int*   ntype = (const int*)d_in[5];
    const int*   etype = (const int*)d_in[6];
    const float* Wmsg  = (const float*)d_in[7];
    const float* Wattr = (const float*)d_in[8];
    const float* Wem   = (const float*)d_in[9];
    const float* Wproj = (const float*)d_in[10];
    const float* Wnode = (const float*)d_in[11];
    const float* Wedge = (const float*)d_in[12];
    const float* cobn  = (const float*)d_in[13];
    const float* cobe  = (const float*)d_in[14];
    float* M = (float*)d_out;

    static cudaStream_t s1 = 0, s2 = 0;
    static cudaEvent_t evF = 0, evZ = 0, evW = 0;
    if (!s1) {   // first call is the (non-captured) correctness run: safe point to create
        cudaStreamCreateWithFlags(&s1, cudaStreamNonBlocking);
        cudaStreamCreateWithFlags(&s2, cudaStreamNonBlocking);
        cudaEventCreateWithFlags(&evF, cudaEventDisableTiming);
        cudaEventCreateWithFlags(&evZ, cudaEventDisableTiming);
        cudaEventCreateWithFlags(&evW, cudaEventDisableTiming);
    }

    // fork
    cudaEventRecord(evF, 0);
    cudaStreamWaitEvent(s1, evF, 0);
    cudaStreamWaitEvent(s2, evF, 0);

    // side branch 1: zero the 676MB output (DRAM-bound, overlaps all compute)
    k_zero<<<592, 256, 0, s1>>>((float4*)M);
    cudaEventRecord(evZ, s1);

    // side branch 2: fused change-of-basis weights (coalesced tiled GEMMs)
    k_pre_node<<<32, 192, 0, s2>>>(Wnode, cobn);
    k_pre_edge<<<40, 192, 0, s2>>>(Wedge, cobe);
    cudaEventRecord(evW, s2);

    // main chain
    k_node_prep<<<NN, FF>>>(nf, na, Wmsg, Wattr);
    k_index<<<1, 1024>>>(ei, etype);
    cudaStreamWaitEvent(0, evW, 0);
    k_node_out<<<NN/NODES8, 160>>>(Wem, Wproj, ntype, ei);
    k_edge_msg<<<1480, 128>>>(ef, ea, Wem, Wproj, ei);
    cudaStreamWaitEvent(0, evZ, 0);
    k_edge_blocks<<<dim3(64, PP+1), 192>>>(ei, M);
}

// round 6
// speedup vs baseline: 1.0770x; 1.0770x over previous
#include <cuda_runtime.h>
#include <math.h>

#define NN 1000
#define FF 128
#define TT 4
#define PP 10
#define DD 13
#define EE 20000
#define EAD 16
#define HH 128
#define KK 64
#define NDIM 13000        // N*D
#define IEDGE 169
#define INODE 91
#define WNS 172           // padded Wn row stride (mult of 4)
#define WCPAD 68          // padded Wc smem row stride (17 float4 groups, odd -> no bank conflicts)
#define WPPAD 132         // padded Wp smem row stride (33 float4 groups, odd)
#define TOT4 42250000     // 169e6 floats / 4
#define NODES8 8

// ---------------- scratch (device globals; no runtime allocation) ----------------
__device__ __align__(16) float g_m[NN*FF];
__device__ float g_base[NN*FF];
__device__ float g_nh[NN*FF];
__device__ float g_r1[NN*HH];
__device__ float g_r2[NN*HH];
__device__ float g_q1[NN*KK];
__device__ float g_q2[NN*KK];
__device__ __align__(16) float g_Wn[TT*FF*WNS];     // [t][f][xy(pad 172)] = W_node @ cob_node
__device__ __align__(16) float g_WcT[PP*IEDGE*KK];  // [p][xy][k]          = (W_edge @ cob_edge)^T
__device__ __align__(16) float g_h[EE*2*KK];        // per-edge [h_ij(64) | h_ji(64)]
__device__ float g_nblk[NN*IEDGE];                  // node diagonal blocks
__device__ int   g_off[PP+1];
__device__ int   g_bucket[EE];
__device__ int   g_rowoff[NN+1];
__device__ int   g_rentry[2*EE];                    // e*2 | flag (flag=1 -> neighbor is src)

// ---------------- zero the whole output (parallel graph branch) ----------------
__global__ void k_zero(float4* __restrict__ M4) {
    int idx = blockIdx.x*blockDim.x + threadIdx.x;
    int nth = gridDim.x*blockDim.x;
    float4 z = make_float4(0.f, 0.f, 0.f, 0.f);
    for (int i = idx; i < TOT4; i += nth) M4[i] = z;
}

// ---------------- fused change-of-basis weights, coalesced tiled form ----------------
__global__ void __launch_bounds__(192) k_pre_node(const float* __restrict__ Wnode,
                                                  const float* __restrict__ cobn) {
    int t  = blockIdx.x & 3;
    int f0 = (blockIdx.x >> 2) * 16;
    int tid = threadIdx.x;   // 192
    __shared__ float Ws[INODE][17];   // [i][f] padded
    for (int j = tid; j < 16*INODE; j += 192) {
        int f = j / INODE, i = j % INODE;
        Ws[i][f] = Wnode[(t*FF + f0 + f)*INODE + i];
    }
    for (int j = tid; j < 16*3; j += 192)      // zero pad cols so float4 reads are benign
        g_Wn[(t*FF + f0 + j/3)*WNS + IEDGE + (j % 3)] = 0.f;
    __syncthreads();
    if (tid >= IEDGE) return;
    float acc[16];
    #pragma unroll
    for (int f = 0; f < 16; f++) acc[f] = 0.f;
    for (int i = 0; i < INODE; i++) {
        float cv = cobn[(t*INODE + i)*IEDGE + tid];   // coalesced
        #pragma unroll
        for (int f = 0; f < 16; f++) acc[f] += cv * Ws[i][f];
    }
    #pragma unroll
    for (int f = 0; f < 16; f++) g_Wn[(t*FF + f0 + f)*WNS + tid] = acc[f];
}

__global__ void __launch_bounds__(192) k_pre_edge(const float* __restrict__ Wedge,
                                                  const float* __restrict__ cobe) {
    int p  = blockIdx.x >> 2;
    int k0 = (blockIdx.x & 3) * 16;
    int tid = threadIdx.x;   // 192
    __shared__ float Ws[IEDGE][17];   // [i][k] padded
    for (int j = tid; j < 16*IEDGE; j += 192) {
        int k = j / IEDGE, i = j % IEDGE;
        Ws[i][k] = Wedge[(p*KK + k0 + k)*IEDGE + i];
    }
    __syncthreads();
    if (tid >= IEDGE) return;
    float acc[16];
    #pragma unroll
    for (int k = 0; k < 16; k++) acc[k] = 0.f;
    for (int i = 0; i < IEDGE; i++) {
        float cv = cobe[((size_t)p*IEDGE + i)*IEDGE + tid];   // coalesced
        #pragma unroll
        for (int k = 0; k < 16; k++) acc[k] += cv * Ws[i][k];
    }
    float4* dst = (float4*)&g_WcT[(p*IEDGE + tid)*KK + k0];
    #pragma unroll
    for (int k4 = 0; k4 < 4; k4++)
        dst[k4] = make_float4(acc[4*k4], acc[4*k4+1], acc[4*k4+2], acc[4*k4+3]);
}

// ---------------- node prep: m = nf@Wmsg, base = nf + na@Wattr ----------------
__global__ void k_node_prep(const float* __restrict__ nf, const float* __restrict__ na,
                            const float* __restrict__ Wmsg, const float* __restrict__ Wattr) {
    int n = blockIdx.x;
    int f = threadIdx.x;   // 128
    int gt = n*FF + f;
    __shared__ float row[FF];
    row[f] = nf[gt];
    __syncthreads();
    float acc = 0.f;
    #pragma unroll 8
    for (int g = 0; g < FF; g++) acc += row[g] * Wmsg[g*FF + f];
    g_m[gt] = acc;
    float b = row[f];
    #pragma unroll
    for (int t = 0; t < TT; t++) b += na[n*TT + t] * Wattr[t*FF + f];
    g_base[gt] = b;
}

// ---------------- fused hist + scan + bucket (single CTA, smem counters) ----------------
__global__ void __launch_bounds__(1024) k_index(const int* __restrict__ ei,
                                                const int* __restrict__ et) {
    __shared__ int rc[1024];
    __shared__ int tc[PP], tcur[PP];
    int tid = threadIdx.x;
    rc[tid] = 0;
    if (tid < PP) tc[tid] = 0;
    __syncthreads();
    for (int e = tid; e < EE; e += 1024) {
        atomicAdd(&rc[ei[e]], 1);
        atomicAdd(&rc[ei[EE + e]], 1);
        atomicAdd(&tc[et[e]], 1);
    }
    __syncthreads();
    int v = rc[tid];
    #pragma unroll
    for (int off = 1; off < 1024; off <<= 1) {
        int t = (tid >= off) ? rc[tid - off] : 0;
        __syncthreads();
        rc[tid] += t;
        __syncthreads();
    }
    int excl = rc[tid] - v;
    if (tid < NN) g_rowoff[tid] = excl;
    if (tid == NN - 1) g_rowoff[NN] = rc[tid];
    __syncthreads();
    rc[tid] = excl;                          // reuse as row cursors
    if (tid == 0) {
        int a = 0;
        for (int p = 0; p < PP; p++) { g_off[p] = a; tcur[p] = a; a += tc[p]; }
        g_off[PP] = a;
    }
    __syncthreads();
    for (int e = tid; e < EE; e += 1024) {
        int p = et[e];
        g_bucket[atomicAdd(&tcur[p], 1)] = e;
        int s = ei[e], d = ei[EE + e];
        g_rentry[atomicAdd(&rc[s], 1)] = e*2;       // row s, neighbor = dst
        g_rentry[atomicAdd(&rc[d], 1)] = e*2 + 1;   // row d, neighbor = src
    }
}

// ---------------- gather aggregation, chain-free: stage neighbor ids in smem ----------------
__global__ void __launch_bounds__(128) k_gather(const int* __restrict__ ei) {
    int n = blockIdx.x;
    int tid = threadIdx.x;   // 128
    __shared__ int others[512];
    int lo = g_rowoff[n], cnt = g_rowoff[n+1] - lo;
    for (int q = tid; q < cnt; q += 128) {      // parallel, independent resolution
        int v = g_rentry[lo + q];
        int e = v >> 1;
        others[q] = ((v & 1) ? ei[e] : ei[EE + e]) * FF;
    }
    __syncthreads();
    float a0 = 0.f, a1 = 0.f, a2 = 0.f, a3 = 0.f;
    int q = 0;
    for (; q + 4 <= cnt; q += 4) {              // 4-way MLP over independent row loads
        a0 += g_m[others[q]   + tid];
        a1 += g_m[others[q+1] + tid];
        a2 += g_m[others[q+2] + tid];
        a3 += g_m[others[q+3] + tid];
    }
    for (; q < cnt; q++) a0 += g_m[others[q] + tid];
    g_nh[n*FF + tid] = g_base[n*FF + tid] + (a0 + a1 + a2 + a3) * 0.05f;
}

// ---------------- per-node outputs, 8 nodes per CTA (weight-load reuse) ----------------
__global__ void __launch_bounds__(160) k_node_out(const float* __restrict__ Wem,
                                                  const float* __restrict__ Wproj,
                                                  const int* __restrict__ ntype) {
    int nb  = blockIdx.x * NODES8;     // 125 blocks
    int tid = threadIdx.x;             // 160
    __shared__ float nh[NODES8][FF];
    __shared__ int types[NODES8];
    for (int i = tid; i < NODES8*FF; i += 160) nh[i >> 7][i & 127] = g_nh[nb*FF + i];
    if (tid < NODES8) types[tid] = ntype[nb + tid];
    __syncthreads();
    int o = tid;
    if (o >= 139) return;              // 32 r1 + 32 r2 + 16 q1 + 16 q2 + 43 nblk tasks
    const float4* w4 = 0; int stride4 = 0, kind, c0;
    if (o < 32)      { c0 = o*4;        w4 = (const float4*)(Wem + c0);             stride4 = HH/4; kind = 0; }
    else if (o < 64) { c0 = (o-32)*4;   w4 = (const float4*)(Wem + FF*HH + c0);     stride4 = HH/4; kind = 1; }
    else if (o < 80) { c0 = (o-64)*4;   w4 = (const float4*)(Wproj + FF*KK + c0);   stride4 = KK/4; kind = 2; }
    else if (o < 96) { c0 = (o-80)*4;   w4 = (const float4*)(Wproj + 2*FF*KK + c0); stride4 = KK/4; kind = 3; }
    else             { c0 = (o-96)*4;   kind = 4; }
    float4 acc[NODES8];
    #pragma unroll
    for (int m = 0; m < NODES8; m++) acc[m] = make_float4(0.f,0.f,0.f,0.f);
    if (kind < 4) {
        #pragma unroll 4
        for (int g = 0; g < FF; g++) {
            float4 w = w4[g*stride4];
            #pragma unroll
            for (int m = 0; m < NODES8; m++) {
                float h = nh[m][g];
                acc[m].x += h*w.x; acc[m].y += h*w.y; acc[m].z += h*w.z; acc[m].w += h*w.w;
            }
        }
    } else {
        const float4* wn[NODES8];
        #pragma unroll
        for (int m = 0; m < NODES8; m++) wn[m] = (const float4*)(g_Wn + types[m]*FF*WNS + c0);
        for (int g = 0; g < FF; g++) {
            #pragma unroll
            for (int m = 0; m < NODES8; m++) {
                float4 w = wn[m][g*(WNS/4)];
                float h = nh[m][g];
                acc[m].x += h*w.x; acc[m].y += h*w.y; acc[m].z += h*w.z; acc[m].w += h*w.w;
            }
        }
    }
    #pragma unroll
    for (int m = 0; m < NODES8; m++) {
        int n = nb + m;
        if (kind == 0)      *(float4*)&g_r1[n*HH + c0] = acc[m];
        else if (kind == 1) *(float4*)&g_r2[n*HH + c0] = acc[m];
        else if (kind == 2) *(float4*)&g_q1[n*KK + c0] = acc[m];
        else if (kind == 3) *(float4*)&g_q2[n*KK + c0] = acc[m];
        else {
            float v[4] = {acc[m].x, acc[m].y, acc[m].z, acc[m].w};
            #pragma unroll
            for (int j = 0; j < 4; j++) {
                int xy = c0 + j;
                if (xy < IEDGE) g_nblk[n*IEDGE + xy] = v[j];
            }
        }
    }
}

// ---------------- per-edge: edge_msg -> u -> h_ij/h_ji (4 edges per iteration) ----------------
__global__ void __launch_bounds__(128) k_edge_msg(const float* __restrict__ ef, const float* __restrict__ ea,
                                                  const float* __restrict__ Wem, const float* __restrict__ Wproj,
                                                  const int* __restrict__ ei) {
    __shared__ __align__(16) float wp[KK*WPPAD];   // [c(64)][g(128) pad 132] W_proj rows 0..127 transposed
    __shared__ __align__(16) float msg[4][HH];
    __shared__ float eatt[4][32];
    __shared__ int sd[8];
    int tid = threadIdx.x;   // 128
    float emreg[32];         // column tid of W_em rows 256..287 (edge feats/attrs part)
    #pragma unroll
    for (int j = 0; j < 32; j++) emreg[j] = Wem[(2*FF + j)*HH + tid];
    for (int i = tid; i < FF*KK; i += 128) {
        int r = i >> 6, c = i & 63;       // coalesced read of Wproj, transpose into smem
        wp[c*WPPAD + r] = Wproj[i];
    }
    __syncthreads();
    for (int grp = blockIdx.x; grp < EE/4; grp += gridDim.x) {
        int e0 = grp*4;
        {
            int el = tid >> 5, j = tid & 31;
            eatt[el][j] = (j < EAD) ? ef[(e0+el)*EAD + j] : ea[(e0+el)*EAD + (j - EAD)];
        }
        if (tid < 8) sd[tid] = ei[(tid & 1)*EE + e0 + (tid >> 1)];
        __syncthreads();
        #pragma unroll
        for (int el = 0; el < 4; el++) {
            float fe = 0.f;
            #pragma unroll
            for (int j = 0; j < 32; j++) fe += eatt[el][j]*emreg[j];
            float pre = g_r1[sd[2*el]*HH + tid] + g_r2[sd[2*el+1]*HH + tid] + fe;
            float ex = __expf(2.f*pre);                  // tanh = 1 - 2/(e^{2x}+1)
            msg[el][tid] = 1.f - __fdividef(2.f, ex + 1.f);
        }
        __syncthreads();
        int c = tid & 63, hh = tid >> 6;
        const float4* wr = (const float4*)&wp[c*WPPAD];
        const float4* m0 = (const float4*)msg[2*hh];
        const float4* m1 = (const float4*)msg[2*hh + 1];
        float u0 = 0.f, u1 = 0.f;
        #pragma unroll 8
        for (int g = 0; g < HH/4; g++) {
            float4 w = wr[g]; float4 a = m0[g]; float4 b = m1[g];
            u0 += w.x*a.x + w.y*a.y + w.z*a.z + w.w*a.w;
            u1 += w.x*b.x + w.y*b.y + w.z*b.z + w.w*b.w;
        }
        #pragma unroll
        for (int q = 0; q < 2; q++) {
            int el = 2*hh + q;
            float u = q ? u1 : u0;
            int e = e0 + el, s = sd[2*el], d = sd[2*el + 1];
            g_h[e*2*KK + c]      = u + g_q1[s*KK + c] + g_q2[d*KK + c];
            g_h[e*2*KK + KK + c] = u + g_q1[d*KK + c] + g_q2[s*KK + c];
        }
        __syncthreads();
    }
}

// ---------------- per-edge 13x13 blocks -> atomic scatter into zeroed M (+ diag blocks) ----------------
__global__ void k_edge_blocks(const int* __restrict__ ei, float* __restrict__ M) {
    int p   = blockIdx.y;
    int tid = threadIdx.x;   // 192
    if (p == PP) {           // diagonal node blocks
        int n0 = blockIdx.x * 16;
        int n1 = min(n0 + 16, NN);
        for (int n = n0; n < n1; n++)
            for (int j = tid; j < IEDGE; j += 192) {
                int x = j/DD, y = j - x*DD;
                atomicAdd(&M[(size_t)(n*DD + x)*NDIM + n*DD + y], g_nblk[n*IEDGE + j]);
            }
        return;
    }
    __shared__ __align__(16) float wc[IEDGE*WCPAD];   // [xy][k pad 68]
    __shared__ __align__(16) float hsm[4*2*KK];       // 4 edges x [h_ij|h_ji]
    __shared__ int einfo[8];
    int beg = g_off[p], end = g_off[p+1];
    int cnt = end - beg;
    int per = (cnt + gridDim.x - 1) / gridDim.x;
    int lo  = beg + blockIdx.x * per;
    int hi  = min(lo + per, end);
    if (lo >= hi) return;   // uniform per block
    const float* srcw = g_WcT + p*IEDGE*KK;
    for (int i = tid; i < IEDGE*(KK/4); i += blockDim.x) {
        int xy = i >> 4, kk = i & 15;
        ((float4*)(wc + xy*WCPAD))[kk] = ((const float4*)(srcw + xy*KK))[kk];
    }
    __syncthreads();
    int x = 0, y = 0, xyt = 0;
    if (tid < IEDGE) { x = tid/DD; y = tid - x*DD; xyt = y*DD + x; }
    for (int base = lo; base < hi; base += 4) {
        int ne = min(4, hi - base);
        for (int i = tid; i < 4*2*KK; i += blockDim.x) {
            int el = i >> 7, off = i & 127;
            float v = 0.f;
            if (el < ne) v = g_h[(size_t)g_bucket[base + el]*2*KK + off];
            hsm[i] = v;
        }
        if (tid < 8) {
            int el = tid >> 1;
            int e = g_bucket[base + min(el, ne - 1)];
            einfo[tid] = ei[(tid & 1)*EE + e];
        }
        __syncthreads();
        if (tid < IEDGE) {
            const float4* wf = (const float4*)(wc + tid*WCPAD);
            const float4* wt = (const float4*)(wc + xyt*WCPAD);
            const float4* h4 = (const float4*)hsm;
            float a[4] = {0.f,0.f,0.f,0.f}, b[4] = {0.f,0.f,0.f,0.f};
            #pragma unroll
            for (int kk = 0; kk < KK/4; kk++) {
                float4 f = wf[kk], t = wt[kk];
                #pragma unroll
                for (int el = 0; el < 4; el++) {
                    float4 hf = h4[el*32 + kk];        // h_ij
                    float4 hb = h4[el*32 + 16 + kk];   // h_ji
                    a[el] += hf.x*f.x + hf.y*f.y + hf.z*f.z + hf.w*f.w;
                    b[el] += hb.x*t.x + hb.y*t.y + hb.z*t.z + hb.w*t.w;
                }
            }
            #pragma unroll
            for (int el = 0; el < 4; el++) {
                if (el < ne) {
                    float v = 0.5f*(a[el] + b[el]);
                    int s = einfo[2*el], d = einfo[2*el + 1];
                    atomicAdd(&M[(size_t)(s*DD + x)*NDIM + d*DD + y], v);
                    atomicAdd(&M[(size_t)(d*DD + y)*NDIM + s*DD + x], v);
                }
            }
        }
        __syncthreads();
    }
}

// ---------------- launcher: fork-join graph; streams/events created once (call 1 = correctness run) ----------------
extern "C" void kernel_launch(void* const* d_in, const int* in_sizes, int n_in,
                              void* d_out, int out_size) {
    const float* nf    = (const float*)d_in[0];
    const float* na    = (const float*)d_in[1];
    const float* ef    = (const float*)d_in[2];
    const float* ea    = (const float*)d_in[3];
    const int*   ei    = (const int*)d_in[4];
    const int*   ntype = (const int*)d_in[5];
    const int*   etype = (const int*)d_in[6];
    const float* Wmsg  = (const float*)d_in[7];
    const float* Wattr = (const float*)d_in[8];
    const float* Wem   = (const float*)d_in[9];
    const float* Wproj = (const float*)d_in[10];
    const float* Wnode = (const float*)d_in[11];
    const float* Wedge = (const float*)d_in[12];
    const float* cobn  = (const float*)d_in[13];
    const float* cobe  = (const float*)d_in[14];
    float* M = (float*)d_out;

    static cudaStream_t s1 = 0, s2 = 0;
    static cudaEvent_t evF = 0, evZ = 0, evW = 0;
    if (!s1) {   // first call is the (non-captured) correctness run: safe point to create
        cudaStreamCreateWithFlags(&s1, cudaStreamNonBlocking);
        cudaStreamCreateWithFlags(&s2, cudaStreamNonBlocking);
        cudaEventCreateWithFlags(&evF, cudaEventDisableTiming);
        cudaEventCreateWithFlags(&evZ, cudaEventDisableTiming);
        cudaEventCreateWithFlags(&evW, cudaEventDisableTiming);
    }

    // fork
    cudaEventRecord(evF, 0);
    cudaStreamWaitEvent(s1, evF, 0);
    cudaStreamWaitEvent(s2, evF, 0);

    // side branch 1: zero the 676MB output (DRAM-bound, overlaps all compute)
    k_zero<<<592, 256, 0, s1>>>((float4*)M);
    cudaEventRecord(evZ, s1);

    // side branch 2: fused change-of-basis weights (coalesced tiled GEMMs)
    k_pre_node<<<32, 192, 0, s2>>>(Wnode, cobn);
    k_pre_edge<<<40, 192, 0, s2>>>(Wedge, cobe);
    cudaEventRecord(evW, s2);

    // main chain
    k_node_prep<<<NN, FF>>>(nf, na, Wmsg, Wattr);
    k_index<<<1, 1024>>>(ei, etype);
    k_gather<<<NN, 128>>>(ei);
    cudaStreamWaitEvent(0, evW, 0);
    k_node_out<<<NN/NODES8, 160>>>(Wem, Wproj, ntype);
    k_edge_msg<<<1480, 128>>>(ef, ea, Wem, Wproj, ei);
    cudaStreamWaitEvent(0, evZ, 0);
    k_edge_blocks<<<dim3(64, PP+1), 192>>>(ei, M);
}

// round 7
// speedup vs baseline: 1.1834x; 1.0988x over previous
#include <cuda_runtime.h>
#include <math.h>
#include <stdint.h>

#define NN 1000
#define FF 128
#define TT 4
#define PP 10
#define DD 13
#define EE 20000
#define EAD 16
#define HH 128
#define KK 64
#define NDIM 13000        // N*D
#define IEDGE 169
#define INODE 91
#define WNS 172           // padded Wn row stride (mult of 4)
#define WCPAD 68          // padded Wc smem row stride (17 float4 groups, odd -> no bank conflicts)
#define WPPAD 132         // padded Wp smem row stride (33 float4 groups, odd)
#define NODES8 8

#define TOTB 676000000u   // bytes of M
#define ZCH  32768u       // TMA chunk
#define NFULL 20629u      // full chunks
#define TAILB 28928u      // remainder bytes (676e6 - 20629*32768), mult of 16

// ---------------- scratch (device globals; no runtime allocation) ----------------
__device__ __align__(16) float g_m[NN*FF];
__device__ float g_base[NN*FF];
__device__ float g_nh[NN*FF];
__device__ float g_r1[NN*HH];
__device__ float g_r2[NN*HH];
__device__ float g_q1[NN*KK];
__device__ float g_q2[NN*KK];
__device__ __align__(16) float g_Wn[TT*FF*WNS];     // [t][f][xy(pad 172)] = W_node @ cob_node
__device__ __align__(16) float g_WcT[PP*IEDGE*KK];  // [p][xy][k]          = (W_edge @ cob_edge)^T
__device__ __align__(16) float g_h[EE*2*KK];        // per-edge [h_ij(64) | h_ji(64)]
__device__ float g_nblk[NN*IEDGE];                  // node diagonal blocks
__device__ int   g_off[PP+1];
__device__ int   g_bucket[EE];
__device__ int   g_rowoff[NN+1];
__device__ int   g_rentry[2*EE];                    // e*2 | flag (flag=1 -> neighbor is src)

// ---------------- zero M via TMA bulk stores (issue-light, DRAM-rate, leaves SMs free) ----------------
__global__ void __launch_bounds__(256) k_zero_tma(char* __restrict__ M) {
    __shared__ __align__(128) float4 zbuf[ZCH/16];   // 32KB of zeros
    int tid = threadIdx.x;
    float4 z = make_float4(0.f, 0.f, 0.f, 0.f);
    #pragma unroll
    for (int i = 0; i < (int)(ZCH/16/256); i++) zbuf[tid + i*256] = z;
    __syncthreads();
    if (tid != 0) return;
    asm volatile("fence.proxy.async.shared::cta;" ::: "memory");
    uint32_t saddr;
    asm("{ .reg .u64 t; cvta.to.shared.u64 t, %1; cvt.u32.u64 %0, t; }" : "=r"(saddr) : "l"(zbuf));
    for (uint32_t c = blockIdx.x; c < NFULL + 1; c += gridDim.x) {
        char* dst = M + (size_t)c * ZCH;
        uint32_t bytes = (c == NFULL) ? TAILB : ZCH;
        asm volatile("cp.async.bulk.global.shared::cta.bulk_group [%0], [%1], %2;"
                     :: "l"(dst), "r"(saddr), "r"(bytes) : "memory");
    }
    asm volatile("cp.async.bulk.commit_group;" ::: "memory");
    asm volatile("cp.async.bulk.wait_group 0;" ::: "memory");
}

// ---------------- fused change-of-basis weights, coalesced tiled form ----------------
__global__ void __launch_bounds__(192) k_pre_node(const float* __restrict__ Wnode,
                                                  const float* __restrict__ cobn) {
    int t  = blockIdx.x & 3;
    int f0 = (blockIdx.x >> 2) * 16;
    int tid = threadIdx.x;   // 192
    __shared__ float Ws[INODE][17];   // [i][f] padded
    for (int j = tid; j < 16*INODE; j += 192) {
        int f = j / INODE, i = j % INODE;
        Ws[i][f] = Wnode[(t*FF + f0 + f)*INODE + i];
    }
    for (int j = tid; j < 16*3; j += 192)      // zero pad cols so float4 reads are benign
        g_Wn[(t*FF + f0 + j/3)*WNS + IEDGE + (j % 3)] = 0.f;
    __syncthreads();
    if (tid >= IEDGE) return;
    float acc[16];
    #pragma unroll
    for (int f = 0; f < 16; f++) acc[f] = 0.f;
    for (int i = 0; i < INODE; i++) {
        float cv = cobn[(t*INODE + i)*IEDGE + tid];   // coalesced
        #pragma unroll
        for (int f = 0; f < 16; f++) acc[f] += cv * Ws[i][f];
    }
    #pragma unroll
    for (int f = 0; f < 16; f++) g_Wn[(t*FF + f0 + f)*WNS + tid] = acc[f];
}

__global__ void __launch_bounds__(192) k_pre_edge(const float* __restrict__ Wedge,
                                                  const float* __restrict__ cobe) {
    int p  = blockIdx.x >> 2;
    int k0 = (blockIdx.x & 3) * 16;
    int tid = threadIdx.x;   // 192
    __shared__ float Ws[IEDGE][17];   // [i][k] padded
    for (int j = tid; j < 16*IEDGE; j += 192) {
        int k = j / IEDGE, i = j % IEDGE;
        Ws[i][k] = Wedge[(p*KK + k0 + k)*IEDGE + i];
    }
    __syncthreads();
    if (tid >= IEDGE) return;
    float acc[16];
    #pragma unroll
    for (int k = 0; k < 16; k++) acc[k] = 0.f;
    for (int i = 0; i < IEDGE; i++) {
        float cv = cobe[((size_t)p*IEDGE + i)*IEDGE + tid];   // coalesced
        #pragma unroll
        for (int k = 0; k < 16; k++) acc[k] += cv * Ws[i][k];
    }
    float4* dst = (float4*)&g_WcT[(p*IEDGE + tid)*KK + k0];
    #pragma unroll
    for (int k4 = 0; k4 < 4; k4++)
        dst[k4] = make_float4(acc[4*k4], acc[4*k4+1], acc[4*k4+2], acc[4*k4+3]);
}

// ---------------- node prep: m = nf@Wmsg, base = nf + na@Wattr ----------------
__global__ void k_node_prep(const float* __restrict__ nf, const float* __restrict__ na,
                            const float* __restrict__ Wmsg, const float* __restrict__ Wattr) {
    int n = blockIdx.x;
    int f = threadIdx.x;   // 128
    int gt = n*FF + f;
    __shared__ float row[FF];
    row[f] = nf[gt];
    __syncthreads();
    float a0 = 0.f, a1 = 0.f, a2 = 0.f, a3 = 0.f;
    #pragma unroll 4
    for (int g = 0; g < FF; g += 4) {   // 4 independent FMA chains
        a0 += row[g]   * Wmsg[(g)*FF + f];
        a1 += row[g+1] * Wmsg[(g+1)*FF + f];
        a2 += row[g+2] * Wmsg[(g+2)*FF + f];
        a3 += row[g+3] * Wmsg[(g+3)*FF + f];
    }
    g_m[gt] = (a0 + a1) + (a2 + a3);
    float b = row[f];
    #pragma unroll
    for (int t = 0; t < TT; t++) b += na[n*TT + t] * Wattr[t*FF + f];
    g_base[gt] = b;
}

// ---------------- fused hist + scan + bucket (single CTA, smem counters) ----------------
__global__ void __launch_bounds__(1024) k_index(const int* __restrict__ ei,
                                                const int* __restrict__ et) {
    __shared__ int rc[1024];
    __shared__ int tc[PP], tcur[PP];
    int tid = threadIdx.x;
    rc[tid] = 0;
    if (tid < PP) tc[tid] = 0;
    __syncthreads();
    for (int e = tid; e < EE; e += 1024) {
        atomicAdd(&rc[ei[e]], 1);
        atomicAdd(&rc[ei[EE + e]], 1);
        atomicAdd(&tc[et[e]], 1);
    }
    __syncthreads();
    int v = rc[tid];
    #pragma unroll
    for (int off = 1; off < 1024; off <<= 1) {
        int t = (tid >= off) ? rc[tid - off] : 0;
        __syncthreads();
        rc[tid] += t;
        __syncthreads();
    }
    int excl = rc[tid] - v;
    if (tid < NN) g_rowoff[tid] = excl;
    if (tid == NN - 1) g_rowoff[NN] = rc[tid];
    __syncthreads();
    rc[tid] = excl;                          // reuse as row cursors
    if (tid == 0) {
        int a = 0;
        for (int p = 0; p < PP; p++) { g_off[p] = a; tcur[p] = a; a += tc[p]; }
        g_off[PP] = a;
    }
    __syncthreads();
    for (int e = tid; e < EE; e += 1024) {
        int p = et[e];
        g_bucket[atomicAdd(&tcur[p], 1)] = e;
        int s = ei[e], d = ei[EE + e];
        g_rentry[atomicAdd(&rc[s], 1)] = e*2;       // row s, neighbor = dst
        g_rentry[atomicAdd(&rc[d], 1)] = e*2 + 1;   // row d, neighbor = src
    }
}

// ---------------- gather aggregation, chain-free: stage neighbor ids in smem ----------------
__global__ void __launch_bounds__(128) k_gather(const int* __restrict__ ei) {
    int n = blockIdx.x;
    int tid = threadIdx.x;   // 128
    __shared__ int others[512];
    int lo = g_rowoff[n], cnt = g_rowoff[n+1] - lo;
    for (int q = tid; q < cnt; q += 128) {      // parallel, independent resolution
        int v = g_rentry[lo + q];
        int e = v >> 1;
        others[q] = ((v & 1) ? ei[e] : ei[EE + e]) * FF;
    }
    __syncthreads();
    float a0 = 0.f, a1 = 0.f, a2 = 0.f, a3 = 0.f;
    int q = 0;
    for (; q + 4 <= cnt; q += 4) {              // 4-way MLP over independent row loads
        a0 += g_m[others[q]   + tid];
        a1 += g_m[others[q+1] + tid];
        a2 += g_m[others[q+2] + tid];
        a3 += g_m[others[q+3] + tid];
    }
    for (; q < cnt; q++) a0 += g_m[others[q] + tid];
    g_nh[n*FF + tid] = g_base[n*FF + tid] + (a0 + a1 + a2 + a3) * 0.05f;
}

// ---------------- per-node outputs, 8 nodes per CTA (weight-load reuse) ----------------
__global__ void __launch_bounds__(160) k_node_out(const float* __restrict__ Wem,
                                                  const float* __restrict__ Wproj,
                                                  const int* __restrict__ ntype) {
    int nb  = blockIdx.x * NODES8;     // 125 blocks
    int tid = threadIdx.x;             // 160
    __shared__ float nh[NODES8][FF];
    __shared__ int types[NODES8];
    for (int i = tid; i < NODES8*FF; i += 160) nh[i >> 7][i & 127] = g_nh[nb*FF + i];
    if (tid < NODES8) types[tid] = ntype[nb + tid];
    __syncthreads();
    int o = tid;
    if (o >= 139) return;              // 32 r1 + 32 r2 + 16 q1 + 16 q2 + 43 nblk tasks
    const float4* w4 = 0; int stride4 = 0, kind, c0;
    if (o < 32)      { c0 = o*4;        w4 = (const float4*)(Wem + c0);             stride4 = HH/4; kind = 0; }
    else if (o < 64) { c0 = (o-32)*4;   w4 = (const float4*)(Wem + FF*HH + c0);     stride4 = HH/4; kind = 1; }
    else if (o < 80) { c0 = (o-64)*4;   w4 = (const float4*)(Wproj + FF*KK + c0);   stride4 = KK/4; kind = 2; }
    else if (o < 96) { c0 = (o-80)*4;   w4 = (const float4*)(Wproj + 2*FF*KK + c0); stride4 = KK/4; kind = 3; }
    else             { c0 = (o-96)*4;   kind = 4; }
    float4 acc[NODES8];
    #pragma unroll
    for (int m = 0; m < NODES8; m++) acc[m] = make_float4(0.f,0.f,0.f,0.f);
    if (kind < 4) {
        #pragma unroll 4
        for (int g = 0; g < FF; g++) {
            float4 w = w4[g*stride4];
            #pragma unroll
            for (int m = 0; m < NODES8; m++) {
                float h = nh[m][g];
                acc[m].x += h*w.x; acc[m].y += h*w.y; acc[m].z += h*w.z; acc[m].w += h*w.w;
            }
        }
    } else {
        const float4* wn[NODES8];
        #pragma unroll
        for (int m = 0; m < NODES8; m++) wn[m] = (const float4*)(g_Wn + types[m]*FF*WNS + c0);
        for (int g = 0; g < FF; g++) {
            #pragma unroll
            for (int m = 0; m < NODES8; m++) {
                float4 w = wn[m][g*(WNS/4)];
                float h = nh[m][g];
                acc[m].x += h*w.x; acc[m].y += h*w.y; acc[m].z += h*w.z; acc[m].w += h*w.w;
            }
        }
    }
    #pragma unroll
    for (int m = 0; m < NODES8; m++) {
        int n = nb + m;
        if (kind == 0)      *(float4*)&g_r1[n*HH + c0] = acc[m];
        else if (kind == 1) *(float4*)&g_r2[n*HH + c0] = acc[m];
        else if (kind == 2) *(float4*)&g_q1[n*KK + c0] = acc[m];
        else if (kind == 3) *(float4*)&g_q2[n*KK + c0] = acc[m];
        else {
            float v[4] = {acc[m].x, acc[m].y, acc[m].z, acc[m].w};
            #pragma unroll
            for (int j = 0; j < 4; j++) {
                int xy = c0 + j;
                if (xy < IEDGE) g_nblk[n*IEDGE + xy] = v[j];
            }
        }
    }
}

// ---------------- per-edge: edge_msg -> u -> h_ij/h_ji (4 edges per iteration) ----------------
__global__ void __launch_bounds__(128) k_edge_msg(const float* __restrict__ ef, const float* __restrict__ ea,
                                                  const float* __restrict__ Wem, const float* __restrict__ Wproj,
                                                  const int* __restrict__ ei) {
    __shared__ __align__(16) float wp[KK*WPPAD];   // [c(64)][g(128) pad 132] W_proj rows 0..127 transposed
    __shared__ __align__(16) float msg[4][HH];
    __shared__ float eatt[4][32];
    __shared__ int sd[8];
    int tid = threadIdx.x;   // 128
    float emreg[32];         // column tid of W_em rows 256..287 (edge feats/attrs part)
    #pragma unroll
    for (int j = 0; j < 32; j++) emreg[j] = Wem[(2*FF + j)*HH + tid];
    for (int i = tid; i < FF*KK; i += 128) {
        int r = i >> 6, c = i & 63;       // coalesced read of Wproj, transpose into smem
        wp[c*WPPAD + r] = Wproj[i];
    }
    __syncthreads();
    for (int grp = blockIdx.x; grp < EE/4; grp += gridDim.x) {
        int e0 = grp*4;
        {
            int el = tid >> 5, j = tid & 31;
            eatt[el][j] = (j < EAD) ? ef[(e0+el)*EAD + j] : ea[(e0+el)*EAD + (j - EAD)];
        }
        if (tid < 8) sd[tid] = ei[(tid & 1)*EE + e0 + (tid >> 1)];
        __syncthreads();
        #pragma unroll
        for (int el = 0; el < 4; el++) {
            float fe = 0.f;
            #pragma unroll
            for (int j = 0; j < 32; j++) fe += eatt[el][j]*emreg[j];
            float pre = g_r1[sd[2*el]*HH + tid] + g_r2[sd[2*el+1]*HH + tid] + fe;
            float ex = __expf(2.f*pre);                  // tanh = 1 - 2/(e^{2x}+1)
            msg[el][tid] = 1.f - __fdividef(2.f, ex + 1.f);
        }
        __syncthreads();
        int c = tid & 63, hh = tid >> 6;
        const float4* wr = (const float4*)&wp[c*WPPAD];
        const float4* m0 = (const float4*)msg[2*hh];
        const float4* m1 = (const float4*)msg[2*hh + 1];
        float u0 = 0.f, u1 = 0.f;
        #pragma unroll 8
        for (int g = 0; g < HH/4; g++) {
            float4 w = wr[g]; float4 a = m0[g]; float4 b = m1[g];
            u0 += w.x*a.x + w.y*a.y + w.z*a.z + w.w*a.w;
            u1 += w.x*b.x + w.y*b.y + w.z*b.z + w.w*b.w;
        }
        #pragma unroll
        for (int q = 0; q < 2; q++) {
            int el = 2*hh + q;
            float u = q ? u1 : u0;
            int e = e0 + el, s = sd[2*el], d = sd[2*el + 1];
            g_h[e*2*KK + c]      = u + g_q1[s*KK + c] + g_q2[d*KK + c];
            g_h[e*2*KK + KK + c] = u + g_q1[d*KK + c] + g_q2[s*KK + c];
        }
        __syncthreads();
    }
}

// ---------------- per-edge 13x13 blocks -> atomic scatter into zeroed M (+ diag blocks) ----------------
__global__ void k_edge_blocks(const int* __restrict__ ei, float* __restrict__ M) {
    int p   = blockIdx.y;
    int tid = threadIdx.x;   // 192
    if (p == PP) {           // diagonal node blocks
        int n0 = blockIdx.x * 16;
        int n1 = min(n0 + 16, NN);
        for (int n = n0; n < n1; n++)
            for (int j = tid; j < IEDGE; j += 192) {
                int x = j/DD, y = j - x*DD;
                atomicAdd(&M[(size_t)(n*DD + x)*NDIM + n*DD + y], g_nblk[n*IEDGE + j]);
            }
        return;
    }
    __shared__ __align__(16) float wc[IEDGE*WCPAD];   // [xy][k pad 68]
    __shared__ __align__(16) float hsm[4*2*KK];       // 4 edges x [h_ij|h_ji]
    __shared__ int einfo[8];
    int beg = g_off[p], end = g_off[p+1];
    int cnt = end - beg;
    int per = (cnt + gridDim.x - 1) / gridDim.x;
    int lo  = beg + blockIdx.x * per;
    int hi  = min(lo + per, end);
    if (lo >= hi) return;   // uniform per block
    const float* srcw = g_WcT + p*IEDGE*KK;
    for (int i = tid; i < IEDGE*(KK/4); i += blockDim.x) {
        int xy = i >> 4, kk = i & 15;
        ((float4*)(wc + xy*WCPAD))[kk] = ((const float4*)(srcw + xy*KK))[kk];
    }
    __syncthreads();
    int x = 0, y = 0, xyt = 0;
    if (tid < IEDGE) { x = tid/DD; y = tid - x*DD; xyt = y*DD + x; }
    for (int base = lo; base < hi; base += 4) {
        int ne = min(4, hi - base);
        for (int i = tid; i < 4*2*KK; i += blockDim.x) {
            int el = i >> 7, off = i & 127;
            float v = 0.f;
            if (el < ne) v = g_h[(size_t)g_bucket[base + el]*2*KK + off];
            hsm[i] = v;
        }
        if (tid < 8) {
            int el = tid >> 1;
            int e = g_bucket[base + min(el, ne - 1)];
            einfo[tid] = ei[(tid & 1)*EE + e];
        }
        __syncthreads();
        if (tid < IEDGE) {
            const float4* wf = (const float4*)(wc + tid*WCPAD);
            const float4* wt = (const float4*)(wc + xyt*WCPAD);
            const float4* h4 = (const float4*)hsm;
            float a[4] = {0.f,0.f,0.f,0.f}, b[4] = {0.f,0.f,0.f,0.f};
            #pragma unroll
            for (int kk = 0; kk < KK/4; kk++) {
                float4 f = wf[kk], t = wt[kk];
                #pragma unroll
                for (int el = 0; el < 4; el++) {
                    float4 hf = h4[el*32 + kk];        // h_ij
                    float4 hb = h4[el*32 + 16 + kk];   // h_ji
                    a[el] += hf.x*f.x + hf.y*f.y + hf.z*f.z + hf.w*f.w;
                    b[el] += hb.x*t.x + hb.y*t.y + hb.z*t.z + hb.w*t.w;
                }
            }
            #pragma unroll
            for (int el = 0; el < 4; el++) {
                if (el < ne) {
                    float v = 0.5f*(a[el] + b[el]);
                    int s = einfo[2*el], d = einfo[2*el + 1];
                    atomicAdd(&M[(size_t)(s*DD + x)*NDIM + d*DD + y], v);
                    atomicAdd(&M[(size_t)(d*DD + y)*NDIM + s*DD + x], v);
                }
            }
        }
        __syncthreads();
    }
}

// ---------------- launcher: fork-join graph; streams/events created once (call 1 = correctness run) ----------------
extern "C" void kernel_launch(void* const* d_in, const int* in_sizes, int n_in,
                              void* d_out, int out_size) {
    const float* nf    = (const float*)d_in[0];
    const float* na    = (const float*)d_in[1];
    const float* ef    = (const float*)d_in[2];
    const float* ea    = (const float*)d_in[3];
    const int*   ei    = (const int*)d_in[4];
    const int*   ntype = (const int*)d_in[5];
    const int*   etype = (const int*)d_in[6];
    const float* Wmsg  = (const float*)d_in[7];
    const float* Wattr = (const float*)d_in[8];
    const float* Wem   = (const float*)d_in[9];
    const float* Wproj = (const float*)d_in[10];
    const float* Wnode = (const float*)d_in[11];
    const float* Wedge = (const float*)d_in[12];
    const float* cobn  = (const float*)d_in[13];
    const float* cobe  = (const float*)d_in[14];
    float* M = (float*)d_out;

    static cudaStream_t s1 = 0, s2 = 0;
    static cudaEvent_t evF = 0, evZ = 0, evW = 0;
    if (!s1) {   // first call is the (non-captured) correctness run: safe point to create
        cudaStreamCreateWithFlags(&s1, cudaStreamNonBlocking);
        cudaStreamCreateWithFlags(&s2, cudaStreamNonBlocking);
        cudaEventCreateWithFlags(&evF, cudaEventDisableTiming);
        cudaEventCreateWithFlags(&evZ, cudaEventDisableTiming);
        cudaEventCreateWithFlags(&evW, cudaEventDisableTiming);
    }

    // fork
    cudaEventRecord(evF, 0);
    cudaStreamWaitEvent(s1, evF, 0);
    cudaStreamWaitEvent(s2, evF, 0);

    // side branch 1: zero 676MB via TMA bulk stores (DRAM-rate, ~32 active threads/SM)
    k_zero_tma<<<148, 256, 0, s1>>>((char*)M);
    cudaEventRecord(evZ, s1);

    // side branch 2: fused change-of-basis weights (coalesced tiled GEMMs)
    k_pre_node<<<32, 192, 0, s2>>>(Wnode, cobn);
    k_pre_edge<<<40, 192, 0, s2>>>(Wedge, cobe);
    cudaEventRecord(evW, s2);

    // main chain
    k_node_prep<<<NN, FF>>>(nf, na, Wmsg, Wattr);
    k_index<<<1, 1024>>>(ei, etype);
    k_gather<<<NN, 128>>>(ei);
    cudaStreamWaitEvent(0, evW, 0);
    k_node_out<<<NN/NODES8, 160>>>(Wem, Wproj, ntype);
    k_edge_msg<<<1480, 128>>>(ef, ea, Wem, Wproj, ei);
    cudaStreamWaitEvent(0, evZ, 0);
    k_edge_blocks<<<dim3(64, PP+1), 192>>>(ei, M);
}